// round 11
// baseline (speedup 1.0000x reference)
#include <cuda_runtime.h>
#include <math.h>

// Problem constants
#define NB   64     // batch
#define NL   32     // caption length
#define NT   31     // decode steps = L-1
#define NV   16000  // vocab
#define NE   512    // ENC = DEC = ATT
#define NP   256    // pixels

// ---------------- device scratch (no allocation allowed) ----------------
__device__ float g_enc [NB * NP * NE];        // [B][P][C]
__device__ float g_att1[NB * NP * NE];        // [B][P][A]
__device__ float g_mean[NB * NE];
__device__ float g_h   [NB * NE];
__device__ float g_c   [NB * NE];
__device__ float g_Hall[NT * NB * NE];        // h2 per step
__device__ float g_xprj[NT * NB * 2048];      // emb gates (INTERLEAVED 4d+g) + biases
__device__ float g_pA  [4 * NB * 3072];       // stepA k-split partials
__device__ float g_awe [NB * NE];
__device__ float g_WA  [3072 * 512];          // [Wdec; Wbeta; Whh interleaved 4d+g]
__device__ float g_WCD [2048 * 512];          // Wih[:,256:768] rows interleaved 4d+g
__device__ float g_Wihx[2048 * 256];          // Wih[:,0:256]   rows interleaved 4d+g
__device__ float g_bsum[2048];                // (b_ih+b_hh) interleaved 4d+g
__device__ int   g_capx[2048];                // emb row per (t,b)
__device__ int   g_rowA[2048];                // active row -> t*64+b (into Hall)
__device__ int   g_rowO[2048];                // active row -> b*31+t (into out)
__device__ int   g_nact[1];

__device__ __forceinline__ float sigf(float x) { return 1.0f / (1.0f + expf(-x)); }

// ============================================================================
// High-throughput SGEMM: C[M,N] = A[M,K] * B[N,K]^T (+bias)  (45 TF/s measured)
// ============================================================================
__global__ void __launch_bounds__(256, 2)
sgemm128(const float* __restrict__ A, int lda, const int* __restrict__ arow,
         const float* __restrict__ B, int ldb,
         const float* __restrict__ bias,
         float* __restrict__ C, int ldc, const int* __restrict__ crow,
         int M, const int* __restrict__ Mdev, int K)
{
    int Mv = Mdev ? *Mdev : M;
    int m0 = blockIdx.x * 128;
    if (m0 >= Mv) return;
    int n0 = blockIdx.y * 128;

    __shared__ float As[2][8][128];
    __shared__ float Bs[2][8][128];

    int tid = threadIdx.x;
    int lrow = tid >> 1;
    int lk4  = (tid & 1) * 4;

    int rowm = m0 + lrow;
    int ca   = (rowm < Mv) ? rowm : (Mv - 1);
    int ar   = arow ? arow[ca] : ca;
    const float* Ap = A + (long long)ar * lda + lk4;
    const float* Bp = B + (long long)(n0 + lrow) * ldb + lk4;

    int tx = tid & 15;
    int ty = tid >> 4;

    float acc[8][8];
#pragma unroll
    for (int i = 0; i < 8; i++)
#pragma unroll
        for (int j = 0; j < 8; j++) acc[i][j] = 0.0f;

    {
        float4 a4 = *(const float4*)Ap;
        float4 b4 = *(const float4*)Bp;
        As[0][lk4 + 0][lrow] = a4.x; As[0][lk4 + 1][lrow] = a4.y;
        As[0][lk4 + 2][lrow] = a4.z; As[0][lk4 + 3][lrow] = a4.w;
        Bs[0][lk4 + 0][lrow] = b4.x; Bs[0][lk4 + 1][lrow] = b4.y;
        Bs[0][lk4 + 2][lrow] = b4.z; Bs[0][lk4 + 3][lrow] = b4.w;
    }
    __syncthreads();

    int ntiles = K >> 3;
    int buf = 0;
    for (int t = 0; t < ntiles; t++) {
        float4 na, nb;
        bool more = (t + 1 < ntiles);
        if (more) {
            int kk = (t + 1) << 3;
            na = *(const float4*)(Ap + kk);
            nb = *(const float4*)(Bp + kk);
        }
#pragma unroll
        for (int k = 0; k < 8; k++) {
            float a[8], b[8];
            *(float4*)(a)     = *(const float4*)&As[buf][k][ty * 4];
            *(float4*)(a + 4) = *(const float4*)&As[buf][k][64 + ty * 4];
            *(float4*)(b)     = *(const float4*)&Bs[buf][k][tx * 4];
            *(float4*)(b + 4) = *(const float4*)&Bs[buf][k][64 + tx * 4];
#pragma unroll
            for (int i = 0; i < 8; i++)
#pragma unroll
                for (int j = 0; j < 8; j++)
                    acc[i][j] = fmaf(a[i], b[j], acc[i][j]);
        }
        if (more) {
            int nbuf = buf ^ 1;
            As[nbuf][lk4 + 0][lrow] = na.x; As[nbuf][lk4 + 1][lrow] = na.y;
            As[nbuf][lk4 + 2][lrow] = na.z; As[nbuf][lk4 + 3][lrow] = na.w;
            Bs[nbuf][lk4 + 0][lrow] = nb.x; Bs[nbuf][lk4 + 1][lrow] = nb.y;
            Bs[nbuf][lk4 + 2][lrow] = nb.z; Bs[nbuf][lk4 + 3][lrow] = nb.w;
            __syncthreads();
            buf = nbuf;
        }
    }

    float bv[8];
#pragma unroll
    for (int jh = 0; jh < 2; jh++)
#pragma unroll
        for (int j = 0; j < 4; j++)
            bv[jh * 4 + j] = bias ? bias[n0 + jh * 64 + tx * 4 + j] : 0.0f;

#pragma unroll
    for (int i = 0; i < 8; i++) {
        int r = m0 + ((i < 4) ? (ty * 4 + i) : (64 + ty * 4 + i - 4));
        if (r >= Mv) continue;
        int cr = crow ? crow[r] : r;
        float* Cp = C + (long long)cr * ldc + n0;
#pragma unroll
        for (int jh = 0; jh < 2; jh++) {
            float4 v;
            v.x = acc[i][jh * 4 + 0] + bv[jh * 4 + 0];
            v.y = acc[i][jh * 4 + 1] + bv[jh * 4 + 1];
            v.z = acc[i][jh * 4 + 2] + bv[jh * 4 + 2];
            v.w = acc[i][jh * 4 + 3] + bv[jh * 4 + 3];
            *(float4*)(Cp + jh * 64 + tx * 4) = v;
        }
    }
}

// ---------------- small tiled SGEMM (h0/c0 only) ----------------------------
__global__ void sgemm64(const float* __restrict__ A, int lda,
                        const float* __restrict__ B, int ldb,
                        const float* __restrict__ bias,
                        float* __restrict__ C, int ldc, int K)
{
    int n0 = blockIdx.y * 64;
    __shared__ float As[16][68];
    __shared__ float Bs[16][68];

    int tid = threadIdx.x;
    int tx = tid & 15, ty = tid >> 4;
    int lm = tid >> 2, lk = (tid & 3) * 4;

    const float* Arow = A + (long long)lm * lda;
    const float* Brow = B + (long long)(n0 + lm) * ldb;

    float acc[4][4];
#pragma unroll
    for (int i = 0; i < 4; i++)
#pragma unroll
        for (int j = 0; j < 4; j++) acc[i][j] = 0.0f;

    for (int kk = 0; kk < K; kk += 16) {
        float4 av = *(const float4*)(Arow + kk + lk);
        float4 bv = *(const float4*)(Brow + kk + lk);
        __syncthreads();
        As[lk + 0][lm] = av.x; As[lk + 1][lm] = av.y;
        As[lk + 2][lm] = av.z; As[lk + 3][lm] = av.w;
        Bs[lk + 0][lm] = bv.x; Bs[lk + 1][lm] = bv.y;
        Bs[lk + 2][lm] = bv.z; Bs[lk + 3][lm] = bv.w;
        __syncthreads();
#pragma unroll
        for (int k = 0; k < 16; k++) {
            float4 a4 = *(const float4*)&As[k][ty * 4];
            float4 b4 = *(const float4*)&Bs[k][tx * 4];
            float aa[4] = {a4.x, a4.y, a4.z, a4.w};
            float bb[4] = {b4.x, b4.y, b4.z, b4.w};
#pragma unroll
            for (int i = 0; i < 4; i++)
#pragma unroll
                for (int j = 0; j < 4; j++) acc[i][j] = fmaf(aa[i], bb[j], acc[i][j]);
        }
    }

#pragma unroll
    for (int i = 0; i < 4; i++) {
        float* Cp = C + (long long)(ty * 4 + i) * ldc + n0 + tx * 4;
#pragma unroll
        for (int j = 0; j < 4; j++)
            Cp[j] = acc[i][j] + bias[n0 + tx * 4 + j];
    }
}

// ---------------- transpose encoder_out [B][C][P] -> enc [B][P][C] ----------
__global__ void transpose_enc(const float* __restrict__ eo, float* __restrict__ enc)
{
    __shared__ float t[32][33];
    int b = blockIdx.z;
    int c0 = blockIdx.x * 32, p0 = blockIdx.y * 32;
    int x = threadIdx.x, y = threadIdx.y;
    for (int i = y; i < 32; i += 8)
        t[i][x] = eo[((long long)b * NE + c0 + i) * NP + p0 + x];
    __syncthreads();
    for (int i = y; i < 32; i += 8)
        enc[((long long)b * NP + p0 + i) * NE + c0 + x] = t[x][i];
}

// ---------------- mean over pixels ------------------------------------------
__global__ void mean_kernel(const float* __restrict__ eo, float* __restrict__ mean)
{
    int row = blockIdx.x * 8 + threadIdx.y;
    int lane = threadIdx.x;
    const float* src = eo + (long long)row * NP;
    float s = 0.0f;
    for (int p = lane; p < NP; p += 32) s += src[p];
#pragma unroll
    for (int o = 16; o > 0; o >>= 1) s += __shfl_xor_sync(0xffffffffu, s, o);
    if (lane == 0) mean[row] = s * (1.0f / NP);
}

// ---------------- setup ------------------------------------------------------
__global__ void setup_kernel(const int* __restrict__ caps, const int* __restrict__ lens,
                             const float* __restrict__ b_ih, const float* __restrict__ b_hh)
{
    int tid = threadIdx.x;
    for (int j = tid; j < 2048; j += 256) {
        int d = j >> 2, g = j & 3;                 // interleaved 4d+g
        g_bsum[j] = b_ih[g * 512 + d] + b_hh[g * 512 + d];
    }
    for (int i = tid; i < NT * NB; i += 256) {
        int t = i / NB, b = i % NB;
        g_capx[i] = caps[b * NL + t];
    }
    __syncthreads();
    if (tid == 0) {
        int cnt = 0;
        for (int t = 0; t < NT; t++)
            for (int b = 0; b < NB; b++)
                if (t < lens[b] - 1) { g_rowA[cnt] = t * NB + b; g_rowO[cnt] = b * NT + t; cnt++; }
        g_nact[0] = cnt;
        for (int i = cnt; i < 2048; i++) { g_rowA[i] = 0; g_rowO[i] = 0; }
    }
}

// ---------------- build stacked/interleaved weights -------------------------
__global__ void wcat_kernel(const float* __restrict__ Wd, const float* __restrict__ Wb,
                            const float* __restrict__ Whh, const float* __restrict__ Wih)
{
    int f4 = blockIdx.x * blockDim.x + threadIdx.x;
    if (f4 < 3072 * 128) {
        int n = f4 >> 7, q = (f4 & 127) * 4;
        const float* src;
        if (n < 512)       src = Wd + n * 512 + q;
        else if (n < 1024) src = Wb + (n - 512) * 512 + q;
        else {
            int m = n - 1024, d = m >> 2, g = m & 3;
            src = Whh + (g * 512 + d) * 512 + q;
        }
        *(float4*)(g_WA + f4 * 4) = *(const float4*)src;
    } else if (f4 < 3072 * 128 + 2048 * 128) {
        int r = f4 - 3072 * 128;
        int n = r >> 7, q = (r & 127) * 4;
        int d = n >> 2, g = n & 3;
        *(float4*)(g_WCD + r * 4) = *(const float4*)(Wih + (g * 512 + d) * 768 + 256 + q);
    } else {
        int r = f4 - 3072 * 128 - 2048 * 128;
        if (r >= 2048 * 64) return;
        int n = r >> 6, q = (r & 63) * 4;
        int d = n >> 2, g = n & 3;
        *(float4*)(g_Wihx + r * 4) = *(const float4*)(Wih + (g * 512 + d) * 768 + q);
    }
}

// ============================================================================
// STEP A: pA[kz] = h @ WA^T partial (96-col tile, 4b x 6n). Grid 128 x 256.
// ============================================================================
__global__ void __launch_bounds__(256)
stepA_kernel()
{
    __shared__ float sh[2560];
    int blk = blockIdx.x;
    int tid = threadIdx.x;

    int nt = blk & 31;                    // n-tile: cols nt*96..+95
    int kz = blk >> 5;                    // 0..3, kchunk 128
    int k0 = kz * 128;
    float (*As)[64] = (float(*)[64])sh;          // [16][64]
    float (*Ws)[96] = (float(*)[96])(sh + 1024); // [16][96]
    int bi = tid & 15;                    // b = bi*4
    int ci = tid >> 4;                    // cols ci*6
    int lrow = tid >> 2, lk = (tid & 3) * 4;
    int wn2 = (tid >> 2) + 64, wk = (tid & 3) * 4;

    float acc[4][6];
#pragma unroll
    for (int i = 0; i < 4; i++)
#pragma unroll
        for (int j = 0; j < 6; j++) acc[i][j] = 0.0f;

    const float* Wbase = g_WA + (long long)nt * 96 * 512 + k0;
    for (int kk = 0; kk < 128; kk += 16) {
        float4 hv = *(const float4*)(g_h + lrow * 512 + k0 + kk + lk);
        float4 w1 = *(const float4*)(Wbase + (long long)lrow * 512 + kk + lk);
        float4 w2 = make_float4(0, 0, 0, 0);
        if (tid < 128)
            w2 = *(const float4*)(Wbase + (long long)wn2 * 512 + kk + wk);
        __syncthreads();
        As[lk + 0][lrow] = hv.x; As[lk + 1][lrow] = hv.y;
        As[lk + 2][lrow] = hv.z; As[lk + 3][lrow] = hv.w;
        Ws[lk + 0][lrow] = w1.x; Ws[lk + 1][lrow] = w1.y;
        Ws[lk + 2][lrow] = w1.z; Ws[lk + 3][lrow] = w1.w;
        if (tid < 128) {
            Ws[wk + 0][wn2] = w2.x; Ws[wk + 1][wn2] = w2.y;
            Ws[wk + 2][wn2] = w2.z; Ws[wk + 3][wn2] = w2.w;
        }
        __syncthreads();
#pragma unroll
        for (int k = 0; k < 16; k++) {
            float a[4], w[6];
            *(float4*)a = *(const float4*)&As[k][bi * 4];
            *(float2*)(w)     = *(const float2*)&Ws[k][ci * 6];
            *(float2*)(w + 2) = *(const float2*)&Ws[k][ci * 6 + 2];
            *(float2*)(w + 4) = *(const float2*)&Ws[k][ci * 6 + 4];
#pragma unroll
            for (int i = 0; i < 4; i++)
#pragma unroll
                for (int j = 0; j < 6; j++)
                    acc[i][j] = fmaf(a[i], w[j], acc[i][j]);
        }
        __syncthreads();
    }
    float* dst = g_pA + ((long long)kz * NB) * 3072 + nt * 96 + ci * 6;
#pragma unroll
    for (int i = 0; i < 4; i++) {
        float* row = dst + (long long)(bi * 4 + i) * 3072;
        *(float2*)(row)     = make_float2(acc[i][0], acc[i][1]);
        *(float2*)(row + 2) = make_float2(acc[i][2], acc[i][3]);
        *(float2*)(row + 4) = make_float2(acc[i][4], acc[i][5]);
    }
}

// ============================================================================
// STEP B: full attention per batch. Grid 64 x 256.
// ============================================================================
__global__ void __launch_bounds__(256)
stepB_kernel(const float* __restrict__ eo,
             const float* __restrict__ b_dec_att,
             const float* __restrict__ w_full,
             const float* __restrict__ b_full,
             const float* __restrict__ b_beta)
{
    __shared__ float sh[1536];
    int b = blockIdx.x;
    int tid = threadIdx.x;
    float* att2_s  = sh;            // 512
    float* w_s     = sh + 512;      // 512
    float* red_s   = sh + 1024;     // 256
    float* alpha_s = sh + 1280;     // 256

    for (int a = tid; a < 512; a += 256) {
        float v = b_dec_att[a];
#pragma unroll
        for (int kz = 0; kz < 4; kz++)
            v += g_pA[((long long)kz * NB + b) * 3072 + a];
        att2_s[a] = v;
        w_s[a] = w_full[a];
    }
    __syncthreads();

    const float* arow = g_att1 + ((long long)b * NP + tid) * NE;
    float acc = 0.0f;
#pragma unroll 4
    for (int a = 0; a < 512; a += 4) {
        float4 v4 = *(const float4*)(arow + a);
        acc = fmaf(fmaxf(v4.x + att2_s[a + 0], 0.0f), w_s[a + 0], acc);
        acc = fmaf(fmaxf(v4.y + att2_s[a + 1], 0.0f), w_s[a + 1], acc);
        acc = fmaf(fmaxf(v4.z + att2_s[a + 2], 0.0f), w_s[a + 2], acc);
        acc = fmaf(fmaxf(v4.w + att2_s[a + 3], 0.0f), w_s[a + 3], acc);
    }
    acc += b_full[0];

    red_s[tid] = acc; __syncthreads();
    for (int s = 128; s > 0; s >>= 1) {
        if (tid < s) red_s[tid] = fmaxf(red_s[tid], red_s[tid + s]);
        __syncthreads();
    }
    float mx = red_s[0]; __syncthreads();
    float ex = expf(acc - mx);
    red_s[tid] = ex; __syncthreads();
    for (int s = 128; s > 0; s >>= 1) {
        if (tid < s) red_s[tid] += red_s[tid + s];
        __syncthreads();
    }
    alpha_s[tid] = ex / red_s[0];
    __syncthreads();

    for (int c = tid; c < 512; c += 256) {
        const float* erow = eo + ((long long)b * NE + c) * NP;
        float s = 0.0f;
#pragma unroll 4
        for (int p = 0; p < NP; p += 4) {
            float4 e4 = *(const float4*)(erow + p);
            s = fmaf(e4.x, alpha_s[p + 0], s);
            s = fmaf(e4.y, alpha_s[p + 1], s);
            s = fmaf(e4.z, alpha_s[p + 2], s);
            s = fmaf(e4.w, alpha_s[p + 3], s);
        }
        float gpre = b_beta[c];
#pragma unroll
        for (int kz = 0; kz < 4; kz++)
            gpre += g_pA[((long long)kz * NB + b) * 3072 + 512 + c];
        g_awe[b * NE + c] = sigf(gpre) * s;
    }
}

// ============================================================================
// STEP C: gates = awe @ WCD^T (32-col tile, full K) + fused LSTM epilogue.
// Grid 64 x 256. Block blk owns interleaved cols [blk*32, +32) = dims blk*8..+7.
// ============================================================================
__global__ void __launch_bounds__(256)
stepC_kernel(const float* __restrict__ xprj_t, float* __restrict__ Hall_t)
{
    __shared__ float As[16][68];
    __shared__ float Ws[16][36];
    __shared__ float red[2048];
    int blk = blockIdx.x;
    int tid = threadIdx.x;

    int bi = tid & 15;                    // b0 = bi*4
    int ci = tid >> 4;                    // c0 = ci*2
    int b0 = bi * 4, c0 = ci * 2;
    int l = tid >> 2, lk = (tid & 3) * 4; // awe loader: row l, k-quad lk
    int wcol = tid >> 2, wk = (tid & 3) * 4;   // W loader (tid<128)
    const float* Wbase = g_WCD + (long long)blk * 32 * 512;

    float acc[4][2];
#pragma unroll
    for (int i = 0; i < 4; i++) { acc[i][0] = 0.0f; acc[i][1] = 0.0f; }

    for (int kk = 0; kk < 512; kk += 16) {
        float4 av = *(const float4*)(g_awe + l * 512 + kk + lk);
        float4 wv = make_float4(0, 0, 0, 0);
        if (tid < 128)
            wv = *(const float4*)(Wbase + (long long)wcol * 512 + kk + wk);
        __syncthreads();
        As[lk + 0][l] = av.x; As[lk + 1][l] = av.y;
        As[lk + 2][l] = av.z; As[lk + 3][l] = av.w;
        if (tid < 128) {
            Ws[wk + 0][wcol] = wv.x; Ws[wk + 1][wcol] = wv.y;
            Ws[wk + 2][wcol] = wv.z; Ws[wk + 3][wcol] = wv.w;
        }
        __syncthreads();
#pragma unroll
        for (int k = 0; k < 16; k++) {
            float a[4];
            *(float4*)a = *(const float4*)&As[k][b0];
            float w0 = Ws[k][c0], w1 = Ws[k][c0 + 1];
#pragma unroll
            for (int i = 0; i < 4; i++) {
                acc[i][0] = fmaf(a[i], w0, acc[i][0]);
                acc[i][1] = fmaf(a[i], w1, acc[i][1]);
            }
        }
    }
    __syncthreads();
#pragma unroll
    for (int i = 0; i < 4; i++) {
        red[(b0 + i) * 32 + c0 + 0] = acc[i][0];
        red[(b0 + i) * 32 + c0 + 1] = acc[i][1];
    }
    __syncthreads();

    // Fused LSTM epilogue: 512 cells (64 b x 8 dims), 2 per thread
#pragma unroll
    for (int r = 0; r < 2; r++) {
        int idx = tid + r * 256;              // 0..511
        int b = idx >> 3, dl = idx & 7;
        const float* gr = &red[b * 32 + dl * 4];
        float gi = gr[0], gf = gr[1], gg = gr[2], go = gr[3];
#pragma unroll
        for (int kz = 0; kz < 4; kz++) {
            float4 pa = *(const float4*)(g_pA + ((long long)kz * NB + b) * 3072
                                         + 1024 + blk * 32 + dl * 4);
            gi += pa.x; gf += pa.y; gg += pa.z; go += pa.w;
        }
        float4 xv = *(const float4*)(xprj_t + b * 2048 + blk * 32 + dl * 4);
        gi += xv.x; gf += xv.y; gg += xv.z; go += xv.w;
        int d = blk * 8 + dl;
        float cp = g_c[b * NE + d];
        float cn = sigf(gf) * cp + sigf(gi) * tanhf(gg);
        float hn = sigf(go) * tanhf(cn);
        g_c[b * NE + d] = cn;
        g_h[b * NE + d] = hn;
        Hall_t[b * NE + d] = hn;
    }
}

// ---------------- host launch -----------------------------------------------
extern "C" void kernel_launch(void* const* d_in, const int* in_sizes, int n_in,
                              void* d_out, int out_size)
{
    const float* eo        = (const float*)d_in[0];
    const int*   caps      = (const int*)  d_in[1];
    const int*   lens      = (const int*)  d_in[2];
    const float* W_enc_att = (const float*)d_in[3];
    const float* b_enc_att = (const float*)d_in[4];
    const float* W_dec_att = (const float*)d_in[5];
    const float* b_dec_att = (const float*)d_in[6];
    const float* w_full    = (const float*)d_in[7];
    const float* b_full    = (const float*)d_in[8];
    const float* emb       = (const float*)d_in[9];
    const float* W_ih      = (const float*)d_in[10];
    const float* W_hh      = (const float*)d_in[11];
    const float* b_ih      = (const float*)d_in[12];
    const float* b_hh      = (const float*)d_in[13];
    const float* W_init_h  = (const float*)d_in[14];
    const float* b_init_h  = (const float*)d_in[15];
    const float* W_init_c  = (const float*)d_in[16];
    const float* b_init_c  = (const float*)d_in[17];
    const float* W_beta    = (const float*)d_in[18];
    const float* b_beta    = (const float*)d_in[19];
    const float* W_fc      = (const float*)d_in[20];
    const float* b_fc      = (const float*)d_in[21];
    float* out = (float*)d_out;

    float *enc, *att1, *mean, *h, *c, *Hall, *xprj, *bsum, *Wihx;
    int *capx, *rowA, *rowO, *nact;
    cudaGetSymbolAddress((void**)&enc,  g_enc);
    cudaGetSymbolAddress((void**)&att1, g_att1);
    cudaGetSymbolAddress((void**)&mean, g_mean);
    cudaGetSymbolAddress((void**)&h,    g_h);
    cudaGetSymbolAddress((void**)&c,    g_c);
    cudaGetSymbolAddress((void**)&Hall, g_Hall);
    cudaGetSymbolAddress((void**)&xprj, g_xprj);
    cudaGetSymbolAddress((void**)&bsum, g_bsum);
    cudaGetSymbolAddress((void**)&Wihx, g_Wihx);
    cudaGetSymbolAddress((void**)&capx, g_capx);
    cudaGetSymbolAddress((void**)&rowA, g_rowA);
    cudaGetSymbolAddress((void**)&rowO, g_rowO);
    cudaGetSymbolAddress((void**)&nact, g_nact);

    cudaMemsetAsync(out, 0, (size_t)out_size * sizeof(float));

    transpose_enc<<<dim3(16, 8, 64), dim3(32, 8)>>>(eo, enc);
    mean_kernel<<<4096, dim3(32, 8)>>>(eo, mean);
    setup_kernel<<<1, 256>>>(caps, lens, b_ih, b_hh);

    // att1 = enc @ W_enc_att^T + b   (M=16384, N=512, K=512)
    sgemm128<<<dim3(128, 4), 256>>>(enc, 512, nullptr, W_enc_att, 512, b_enc_att,
                                    att1, 512, nullptr, NB * NP, nullptr, 512);

    wcat_kernel<<<3072, 256>>>(W_dec_att, W_beta, W_hh, W_ih);

    sgemm64<<<dim3(1, 8), 256>>>(mean, 512, W_init_h, 512, b_init_h, h, 512, 512);
    sgemm64<<<dim3(1, 8), 256>>>(mean, 512, W_init_c, 512, b_init_c, c, 512, 512);

    // x_proj = emb[cap] @ Wihx^T + bsum (interleaved), K=256
    sgemm128<<<dim3(16, 16), 256>>>(emb, 256, capx, Wihx, 256, bsum,
                                    xprj, 2048, nullptr, NT * NB, nullptr, 256);

    // 31-step recurrence: 3 kernels per step (graph nodes give the ordering)
    for (int t = 0; t < NT; t++) {
        stepA_kernel<<<128, 256>>>();
        stepB_kernel<<<64, 256>>>(eo, b_dec_att, w_full, b_full, b_beta);
        stepC_kernel<<<64, 256>>>(xprj + (long long)t * NB * 2048,
                                  Hall + (long long)t * NB * NE);
    }

    // Final FC over compacted active rows
    sgemm128<<<dim3(16, 125), 256>>>(Hall, 512, rowA, W_fc, 512, b_fc,
                                     out, NV, rowO, NT * NB, nact, 512);
}

// round 13
// speedup vs baseline: 1.4052x; 1.4052x over previous
#include <cuda_runtime.h>
#include <cuda_bf16.h>
#include <stdint.h>
#include <math.h>

// Problem constants
#define NB   64     // batch
#define NL   32     // caption length
#define NT   31     // decode steps = L-1
#define NV   16000  // vocab
#define NE   512    // ENC = DEC = ATT
#define NP   256    // pixels

#define GRIDN 128   // persistent kernel blocks (co-resident, 1 per SM)

// ---------------- device scratch (no allocation allowed) ----------------
__device__ float g_enc [NB * NP * NE];        // [B][P][C]
__device__ float g_att1[NB * NP * NE];        // [B][P][A]
__device__ float g_mean[NB * NE];
__device__ float g_h   [NB * NE];
__device__ float g_c   [NB * NE];
__device__ float g_Hall[NT * NB * NE];        // h2 per step
__device__ float g_xprj[NT * NB * 2048];      // emb gates (INTERLEAVED 4d+g) + biases
__device__ float g_pA  [4 * NB * 3072];       // phase-A k-split partials
__device__ float g_pC  [4 * NB * 2048];       // phase-C k-split partials
__device__ float g_e   [NB * NP];             // attention scores
__device__ float g_awe [NB * NE];
__device__ float g_WA  [3072 * 512];          // [Wdec; Wbeta; Whh interleaved 4d+g]
__device__ float g_WCD [2048 * 512];          // Wih[:,256:768] rows interleaved 4d+g
__device__ float g_Wihx[2048 * 256];          // Wih[:,0:256]   rows interleaved 4d+g
__device__ float g_bsum[2048];                // (b_ih+b_hh) interleaved 4d+g
__device__ int   g_capx[2048];                // emb row per (t,b)
__device__ int   g_rowA[2048];                // active row -> t*64+b (into Hall)
__device__ int   g_rowO[2048];                // active row -> b*31+t (into out)
__device__ int   g_nact[1];
__device__ unsigned g_cnt;                    // barrier arrivals
__device__ unsigned g_rel;                    // barrier release phase

__device__ __forceinline__ float sigf(float x) { return 1.0f / (1.0f + expf(-x)); }

// ============================================================================
// Tensor-core GEMM with bf16 hi/lo split (fp32-grade accuracy, ~4e-6 rel):
// C[M,N] = A[M,K] * B[N,K]^T (+bias), A rows gathered, C rows scattered.
// Tile 128x64, BK=16, 256 threads = 8 warps (4m x 2n), each warp 2x m16 strips
// x 4x n8 tiles, 3 MMAs per tile (hi*hi + hi*lo + lo*hi).
// ============================================================================
#define MMA_BF16(d, A0, A1, A2, A3, B0, B1)                                   \
    asm volatile("mma.sync.aligned.m16n8k16.row.col.f32.bf16.bf16.f32 "       \
                 "{%0,%1,%2,%3}, {%4,%5,%6,%7}, {%8,%9}, {%0,%1,%2,%3};"      \
                 : "+f"(d[0]), "+f"(d[1]), "+f"(d[2]), "+f"(d[3])             \
                 : "r"(A0), "r"(A1), "r"(A2), "r"(A3), "r"(B0), "r"(B1))

__device__ __forceinline__ void bsplit4(__nv_bfloat16* hi, __nv_bfloat16* lo, float4 v)
{
    float f[4] = {v.x, v.y, v.z, v.w};
#pragma unroll
    for (int i = 0; i < 4; i++) {
        __nv_bfloat16 h = __float2bfloat16(f[i]);
        hi[i] = h;
        lo[i] = __float2bfloat16(f[i] - __bfloat162float(h));
    }
}

__global__ void __launch_bounds__(256, 2)
tgemm(const float* __restrict__ A, int lda, const int* __restrict__ arow,
      const float* __restrict__ B, int ldb, const float* __restrict__ bias,
      float* __restrict__ C, int ldc, const int* __restrict__ crow,
      int M, const int* __restrict__ Mdev, int K)
{
    int Mv = Mdev ? *Mdev : M;
    int m0 = blockIdx.x * 128;
    if (m0 >= Mv) return;
    int n0 = blockIdx.y * 64;

    __shared__ __nv_bfloat16 Ah[128][16], Al[128][16];
    __shared__ __nv_bfloat16 Bh[64][16],  Bl[64][16];

    int tid = threadIdx.x;
    int warp = tid >> 5, lane = tid & 31;
    int g = lane >> 2, t4 = lane & 3;
    int wm = warp >> 1, wn = warp & 1;

    // loaders: A rows (tid>>2) and (tid>>2)+64, k-chunk (tid&3)*4; B row tid>>2
    int lr = tid >> 2;
    int ak = (tid & 3) * 4;
    int r0 = m0 + lr, r1 = m0 + lr + 64;
    int c0r = (r0 < Mv) ? r0 : Mv - 1;
    int c1r = (r1 < Mv) ? r1 : Mv - 1;
    int ga0 = arow ? arow[c0r] : c0r;
    int ga1 = arow ? arow[c1r] : c1r;
    const float* Ap0 = A + (long long)ga0 * lda + ak;
    const float* Ap1 = A + (long long)ga1 * lda + ak;
    const float* Bp  = B + (long long)(n0 + lr) * ldb + ak;

    float acc[2][4][4];
#pragma unroll
    for (int s = 0; s < 2; s++)
#pragma unroll
        for (int nt = 0; nt < 4; nt++)
#pragma unroll
            for (int i = 0; i < 4; i++) acc[s][nt][i] = 0.0f;

    for (int k0 = 0; k0 < K; k0 += 16) {
        float4 av0 = *(const float4*)(Ap0 + k0);
        float4 av1 = *(const float4*)(Ap1 + k0);
        float4 bv  = *(const float4*)(Bp + k0);
        __syncthreads();
        bsplit4(&Ah[lr][ak],      &Al[lr][ak],      av0);
        bsplit4(&Ah[lr + 64][ak], &Al[lr + 64][ak], av1);
        bsplit4(&Bh[lr][ak],      &Bl[lr][ak],      bv);
        __syncthreads();

        // B fragments for this warp's 4 n-tiles
        uint32_t bh0[4], bh1[4], bl0[4], bl1[4];
#pragma unroll
        for (int nt = 0; nt < 4; nt++) {
            int n = wn * 32 + nt * 8 + g;
            bh0[nt] = *(const uint32_t*)&Bh[n][2 * t4];
            bh1[nt] = *(const uint32_t*)&Bh[n][2 * t4 + 8];
            bl0[nt] = *(const uint32_t*)&Bl[n][2 * t4];
            bl1[nt] = *(const uint32_t*)&Bl[n][2 * t4 + 8];
        }
#pragma unroll
        for (int s = 0; s < 2; s++) {
            int rs = wm * 32 + s * 16;
            uint32_t ah0 = *(const uint32_t*)&Ah[rs + g][2 * t4];
            uint32_t ah1 = *(const uint32_t*)&Ah[rs + g + 8][2 * t4];
            uint32_t ah2 = *(const uint32_t*)&Ah[rs + g][2 * t4 + 8];
            uint32_t ah3 = *(const uint32_t*)&Ah[rs + g + 8][2 * t4 + 8];
            uint32_t al0 = *(const uint32_t*)&Al[rs + g][2 * t4];
            uint32_t al1 = *(const uint32_t*)&Al[rs + g + 8][2 * t4];
            uint32_t al2 = *(const uint32_t*)&Al[rs + g][2 * t4 + 8];
            uint32_t al3 = *(const uint32_t*)&Al[rs + g + 8][2 * t4 + 8];
#pragma unroll
            for (int nt = 0; nt < 4; nt++) {
                MMA_BF16(acc[s][nt], ah0, ah1, ah2, ah3, bh0[nt], bh1[nt]);
                MMA_BF16(acc[s][nt], ah0, ah1, ah2, ah3, bl0[nt], bl1[nt]);
                MMA_BF16(acc[s][nt], al0, al1, al2, al3, bh0[nt], bh1[nt]);
            }
        }
    }

    // epilogue
#pragma unroll
    for (int s = 0; s < 2; s++) {
#pragma unroll
        for (int half = 0; half < 2; half++) {      // c0/c1 then c2/c3 (row +8)
            int r = m0 + wm * 32 + s * 16 + g + half * 8;
            if (r >= Mv) continue;
            int cr = crow ? crow[r] : r;
#pragma unroll
            for (int nt = 0; nt < 4; nt++) {
                int col = n0 + wn * 32 + nt * 8 + 2 * t4;
                float2 v;
                v.x = acc[s][nt][half * 2 + 0];
                v.y = acc[s][nt][half * 2 + 1];
                if (bias) { v.x += bias[col]; v.y += bias[col + 1]; }
                *(float2*)(C + (long long)cr * ldc + col) = v;
            }
        }
    }
}

// ---------------- small tiled SGEMM (h0/c0 only) ----------------------------
__global__ void sgemm64(const float* __restrict__ A, int lda,
                        const float* __restrict__ B, int ldb,
                        const float* __restrict__ bias,
                        float* __restrict__ C, int ldc, int K)
{
    int n0 = blockIdx.y * 64;
    __shared__ float As[16][68];
    __shared__ float Bs[16][68];

    int tid = threadIdx.x;
    int tx = tid & 15, ty = tid >> 4;
    int lm = tid >> 2, lk = (tid & 3) * 4;

    const float* Arow = A + (long long)lm * lda;
    const float* Brow = B + (long long)(n0 + lm) * ldb;

    float acc[4][4];
#pragma unroll
    for (int i = 0; i < 4; i++)
#pragma unroll
        for (int j = 0; j < 4; j++) acc[i][j] = 0.0f;

    for (int kk = 0; kk < K; kk += 16) {
        float4 av = *(const float4*)(Arow + kk + lk);
        float4 bv = *(const float4*)(Brow + kk + lk);
        __syncthreads();
        As[lk + 0][lm] = av.x; As[lk + 1][lm] = av.y;
        As[lk + 2][lm] = av.z; As[lk + 3][lm] = av.w;
        Bs[lk + 0][lm] = bv.x; Bs[lk + 1][lm] = bv.y;
        Bs[lk + 2][lm] = bv.z; Bs[lk + 3][lm] = bv.w;
        __syncthreads();
#pragma unroll
        for (int k = 0; k < 16; k++) {
            float4 a4 = *(const float4*)&As[k][ty * 4];
            float4 b4 = *(const float4*)&Bs[k][tx * 4];
            float aa[4] = {a4.x, a4.y, a4.z, a4.w};
            float bb[4] = {b4.x, b4.y, b4.z, b4.w};
#pragma unroll
            for (int i = 0; i < 4; i++)
#pragma unroll
                for (int j = 0; j < 4; j++) acc[i][j] = fmaf(aa[i], bb[j], acc[i][j]);
        }
    }

#pragma unroll
    for (int i = 0; i < 4; i++) {
        float* Cp = C + (long long)(ty * 4 + i) * ldc + n0 + tx * 4;
#pragma unroll
        for (int j = 0; j < 4; j++)
            Cp[j] = acc[i][j] + bias[n0 + tx * 4 + j];
    }
}

// ---------------- transpose encoder_out [B][C][P] -> enc [B][P][C] ----------
__global__ void transpose_enc(const float* __restrict__ eo, float* __restrict__ enc)
{
    __shared__ float t[32][33];
    int b = blockIdx.z;
    int c0 = blockIdx.x * 32, p0 = blockIdx.y * 32;
    int x = threadIdx.x, y = threadIdx.y;
    for (int i = y; i < 32; i += 8)
        t[i][x] = eo[((long long)b * NE + c0 + i) * NP + p0 + x];
    __syncthreads();
    for (int i = y; i < 32; i += 8)
        enc[((long long)b * NP + p0 + i) * NE + c0 + x] = t[x][i];
}

// ---------------- mean over pixels ------------------------------------------
__global__ void mean_kernel(const float* __restrict__ eo, float* __restrict__ mean)
{
    int row = blockIdx.x * 8 + threadIdx.y;
    int lane = threadIdx.x;
    const float* src = eo + (long long)row * NP;
    float s = 0.0f;
    for (int p = lane; p < NP; p += 32) s += src[p];
#pragma unroll
    for (int o = 16; o > 0; o >>= 1) s += __shfl_xor_sync(0xffffffffu, s, o);
    if (lane == 0) mean[row] = s * (1.0f / NP);
}

// ---------------- setup ------------------------------------------------------
__global__ void setup_kernel(const int* __restrict__ caps, const int* __restrict__ lens,
                             const float* __restrict__ b_ih, const float* __restrict__ b_hh)
{
    int tid = threadIdx.x;
    for (int j = tid; j < 2048; j += 256) {
        int d = j >> 2, g = j & 3;                 // interleaved 4d+g
        g_bsum[j] = b_ih[g * 512 + d] + b_hh[g * 512 + d];
    }
    for (int i = tid; i < NT * NB; i += 256) {
        int t = i / NB, b = i % NB;
        g_capx[i] = caps[b * NL + t];
    }
    __syncthreads();
    if (tid == 0) {
        int cnt = 0;
        for (int t = 0; t < NT; t++)
            for (int b = 0; b < NB; b++)
                if (t < lens[b] - 1) { g_rowA[cnt] = t * NB + b; g_rowO[cnt] = b * NT + t; cnt++; }
        g_nact[0] = cnt;
        for (int i = cnt; i < 2048; i++) { g_rowA[i] = 0; g_rowO[i] = 0; }
    }
}

// ---------------- build stacked/interleaved weights -------------------------
__global__ void wcat_kernel(const float* __restrict__ Wd, const float* __restrict__ Wb,
                            const float* __restrict__ Whh, const float* __restrict__ Wih)
{
    int f4 = blockIdx.x * blockDim.x + threadIdx.x;
    if (f4 < 3072 * 128) {
        int n = f4 >> 7, q = (f4 & 127) * 4;
        const float* src;
        if (n < 512)       src = Wd + n * 512 + q;
        else if (n < 1024) src = Wb + (n - 512) * 512 + q;
        else {
            int m = n - 1024, d = m >> 2, g = m & 3;
            src = Whh + (g * 512 + d) * 512 + q;
        }
        *(float4*)(g_WA + f4 * 4) = *(const float4*)src;
    } else if (f4 < 3072 * 128 + 2048 * 128) {
        int r = f4 - 3072 * 128;
        int n = r >> 7, q = (r & 127) * 4;
        int d = n >> 2, g = n & 3;
        *(float4*)(g_WCD + r * 4) = *(const float4*)(Wih + (g * 512 + d) * 768 + 256 + q);
    } else {
        int r = f4 - 3072 * 128 - 2048 * 128;
        if (r >= 2048 * 64) return;
        int n = r >> 6, q = (r & 63) * 4;
        int d = n >> 2, g = n & 3;
        *(float4*)(g_Wihx + r * 4) = *(const float4*)(Wih + (g * 512 + d) * 768 + q);
    }
}

// ============================================================================
// PERSISTENT RECURRENCE KERNEL — exact best-measured (2460us) version
// ============================================================================
__device__ __forceinline__ void gbar(unsigned target)
{
    __syncthreads();
    if (threadIdx.x == 0) {
        __threadfence();
        unsigned p = atomicAdd(&g_cnt, 1u);
        if (p == target * GRIDN - 1u) {
            atomicExch(&g_rel, target);
        } else {
            volatile unsigned* rel = &g_rel;
            while (*rel < target) { }
        }
        __threadfence();
    }
    __syncthreads();
}

__global__ void __launch_bounds__(256, 1)
recurrence_kernel(const float* __restrict__ eo,
                  const float* __restrict__ b_dec_att,
                  const float* __restrict__ w_full,
                  const float* __restrict__ b_full,
                  const float* __restrict__ b_beta)
{
    __shared__ float sh[2560];
    int blk = blockIdx.x;
    int tid = threadIdx.x;

    for (int t = 0; t < NT; t++) {
        unsigned base = (unsigned)(t * 5);

        // ======== Phase A: pA[kz] = h @ WA^T partial (96-col tile, 4b x 6n) =====
        {
            int nt = blk & 31;
            int kz = blk >> 5;
            int k0 = kz * 128;
            float (*As)[64] = (float(*)[64])sh;
            float (*Ws)[96] = (float(*)[96])(sh + 1024);
            int bi = tid & 15;
            int ci = tid >> 4;
            int lrow = tid >> 2, lk = (tid & 3) * 4;
            int wn2 = (tid >> 2) + 64, wk = (tid & 3) * 4;

            float acc[4][6];
#pragma unroll
            for (int i = 0; i < 4; i++)
#pragma unroll
                for (int j = 0; j < 6; j++) acc[i][j] = 0.0f;

            const float* Wbase = g_WA + (long long)nt * 96 * 512 + k0;
            for (int kk = 0; kk < 128; kk += 16) {
                float4 hv = *(const float4*)(g_h + lrow * 512 + k0 + kk + lk);
                float4 w1 = *(const float4*)(Wbase + (long long)lrow * 512 + kk + lk);
                float4 w2 = make_float4(0, 0, 0, 0);
                if (tid < 128)
                    w2 = *(const float4*)(Wbase + (long long)wn2 * 512 + kk + wk);
                __syncthreads();
                As[lk + 0][lrow] = hv.x; As[lk + 1][lrow] = hv.y;
                As[lk + 2][lrow] = hv.z; As[lk + 3][lrow] = hv.w;
                Ws[lk + 0][lrow] = w1.x; Ws[lk + 1][lrow] = w1.y;
                Ws[lk + 2][lrow] = w1.z; Ws[lk + 3][lrow] = w1.w;
                if (tid < 128) {
                    Ws[wk + 0][wn2] = w2.x; Ws[wk + 1][wn2] = w2.y;
                    Ws[wk + 2][wn2] = w2.z; Ws[wk + 3][wn2] = w2.w;
                }
                __syncthreads();
#pragma unroll
                for (int k = 0; k < 16; k++) {
                    float a[4], w[6];
                    *(float4*)a = *(const float4*)&As[k][bi * 4];
                    *(float2*)(w)     = *(const float2*)&Ws[k][ci * 6];
                    *(float2*)(w + 2) = *(const float2*)&Ws[k][ci * 6 + 2];
                    *(float2*)(w + 4) = *(const float2*)&Ws[k][ci * 6 + 4];
#pragma unroll
                    for (int i = 0; i < 4; i++)
#pragma unroll
                        for (int j = 0; j < 6; j++)
                            acc[i][j] = fmaf(a[i], w[j], acc[i][j]);
                }
                __syncthreads();
            }
            float* dst = g_pA + ((long long)kz * NB) * 3072 + nt * 96 + ci * 6;
#pragma unroll
            for (int i = 0; i < 4; i++) {
                float* row = dst + (long long)(bi * 4 + i) * 3072;
#pragma unroll
                for (int j = 0; j < 6; j += 2)
                    *(float2*)(row + j) = make_float2(acc[i][j], acc[i][j + 1]);
            }
        }
        gbar(base + 1);

        // ======== Phase B1: e[b][p] scores (b x p-half per block) ================
        {
            int b = blk >> 1, half = blk & 1;
            float* att2_s = sh;
            float* w_s    = sh + 512;
            for (int a = tid; a < 512; a += 256) {
                float v = b_dec_att[a];
#pragma unroll
                for (int kz = 0; kz < 4; kz++)
                    v += g_pA[((long long)kz * NB + b) * 3072 + a];
                att2_s[a] = v;
                w_s[a] = w_full[a];
            }
            __syncthreads();

            int pl = tid >> 1;
            int p  = half * 128 + pl;
            int ao = (tid & 1) * 256;
            const float* arow = g_att1 + ((long long)b * NP + p) * NE + ao;
            float acc = 0.0f;
#pragma unroll 4
            for (int a = 0; a < 256; a += 4) {
                float4 v4 = *(const float4*)(arow + a);
                acc = fmaf(fmaxf(v4.x + att2_s[ao + a + 0], 0.0f), w_s[ao + a + 0], acc);
                acc = fmaf(fmaxf(v4.y + att2_s[ao + a + 1], 0.0f), w_s[ao + a + 1], acc);
                acc = fmaf(fmaxf(v4.z + att2_s[ao + a + 2], 0.0f), w_s[ao + a + 2], acc);
                acc = fmaf(fmaxf(v4.w + att2_s[ao + a + 3], 0.0f), w_s[ao + a + 3], acc);
            }
            acc += __shfl_xor_sync(0xffffffffu, acc, 1);
            if ((tid & 1) == 0) g_e[b * NP + p] = acc + b_full[0];
        }
        gbar(base + 2);

        // ======== Phase B2: softmax + gated awe (b x c-half per block) ===========
        {
            int b = blk >> 1, ch = blk & 1;
            float* es     = sh;
            float* red_s  = sh + 256;
            float* alpha_s= sh + 512;
            es[tid] = g_e[b * NP + tid];
            __syncthreads();
            red_s[tid] = es[tid]; __syncthreads();
            for (int s = 128; s > 0; s >>= 1) {
                if (tid < s) red_s[tid] = fmaxf(red_s[tid], red_s[tid + s]);
                __syncthreads();
            }
            float mx = red_s[0]; __syncthreads();
            float ex = expf(es[tid] - mx);
            red_s[tid] = ex; __syncthreads();
            for (int s = 128; s > 0; s >>= 1) {
                if (tid < s) red_s[tid] += red_s[tid + s];
                __syncthreads();
            }
            alpha_s[tid] = ex / red_s[0];
            __syncthreads();

            int c = ch * 256 + tid;
            const float* erow = eo + ((long long)b * NE + c) * NP;
            float s = 0.0f;
#pragma unroll 4
            for (int p = 0; p < NP; p += 4) {
                float4 e4 = *(const float4*)(erow + p);
                s = fmaf(e4.x, alpha_s[p + 0], s);
                s = fmaf(e4.y, alpha_s[p + 1], s);
                s = fmaf(e4.z, alpha_s[p + 2], s);
                s = fmaf(e4.w, alpha_s[p + 3], s);
            }
            float gpre = b_beta[c];
#pragma unroll
            for (int kz = 0; kz < 4; kz++)
                gpre += g_pA[((long long)kz * NB + b) * 3072 + 512 + c];
            g_awe[b * NE + c] = sigf(gpre) * s;
        }
        gbar(base + 3);

        // ======== Phase C: pC[kz] = awe @ WCD^T partial (64-col tile, 4b x 4n) ===
        {
            int nt = blk & 31;
            int kz = blk >> 5;
            int k0 = kz * 128;
            float (*As)[64] = (float(*)[64])sh;
            float (*Ws)[64] = (float(*)[64])(sh + 1024);
            int bi = tid & 15;
            int ci = tid >> 4;
            int lrow = tid >> 2, lk = (tid & 3) * 4;

            float acc[4][4];
#pragma unroll
            for (int i = 0; i < 4; i++)
#pragma unroll
                for (int j = 0; j < 4; j++) acc[i][j] = 0.0f;

            const float* Wbase = g_WCD + (long long)nt * 64 * 512 + k0;
            for (int kk = 0; kk < 128; kk += 16) {
                float4 av = *(const float4*)(g_awe + lrow * 512 + k0 + kk + lk);
                float4 wv = *(const float4*)(Wbase + (long long)lrow * 512 + kk + lk);
                __syncthreads();
                As[lk + 0][lrow] = av.x; As[lk + 1][lrow] = av.y;
                As[lk + 2][lrow] = av.z; As[lk + 3][lrow] = av.w;
                Ws[lk + 0][lrow] = wv.x; Ws[lk + 1][lrow] = wv.y;
                Ws[lk + 2][lrow] = wv.z; Ws[lk + 3][lrow] = wv.w;
                __syncthreads();
#pragma unroll
                for (int k = 0; k < 16; k++) {
                    float a[4], w[4];
                    *(float4*)a = *(const float4*)&As[k][bi * 4];
                    *(float4*)w = *(const float4*)&Ws[k][ci * 4];
#pragma unroll
                    for (int i = 0; i < 4; i++)
#pragma unroll
                        for (int j = 0; j < 4; j++)
                            acc[i][j] = fmaf(a[i], w[j], acc[i][j]);
                }
                __syncthreads();
            }
            float* dst = g_pC + ((long long)kz * NB) * 2048 + nt * 64 + ci * 4;
#pragma unroll
            for (int i = 0; i < 4; i++)
                *(float4*)(dst + (long long)(bi * 4 + i) * 2048) =
                    make_float4(acc[i][0], acc[i][1], acc[i][2], acc[i][3]);
        }
        gbar(base + 4);

        // ======== Phase D: reduce partials + LSTM pointwise =====================
        {
            int idx = blk * 256 + tid;
            int b = idx >> 9, d = idx & 511;
            float4 gv = *(const float4*)(g_xprj + (((long long)t * NB + b) * 2048) + 4 * d);
            float gi = gv.x, gf = gv.y, gg = gv.z, go = gv.w;
#pragma unroll
            for (int kz = 0; kz < 4; kz++) {
                float4 pa = *(const float4*)(g_pA + ((long long)kz * NB + b) * 3072 + 1024 + 4 * d);
                float4 pc = *(const float4*)(g_pC + ((long long)kz * NB + b) * 2048 + 4 * d);
                gi += pa.x + pc.x; gf += pa.y + pc.y;
                gg += pa.z + pc.z; go += pa.w + pc.w;
            }
            float cp = g_c[b * NE + d];
            float cn = sigf(gf) * cp + sigf(gi) * tanhf(gg);
            float hn = sigf(go) * tanhf(cn);
            g_c[b * NE + d] = cn;
            g_h[b * NE + d] = hn;
            g_Hall[((long long)t * NB + b) * NE + d] = hn;
        }
        gbar(base + 5);
    }
}

// ---------------- host launch -----------------------------------------------
extern "C" void kernel_launch(void* const* d_in, const int* in_sizes, int n_in,
                              void* d_out, int out_size)
{
    const float* eo        = (const float*)d_in[0];
    const int*   caps      = (const int*)  d_in[1];
    const int*   lens      = (const int*)  d_in[2];
    const float* W_enc_att = (const float*)d_in[3];
    const float* b_enc_att = (const float*)d_in[4];
    const float* W_dec_att = (const float*)d_in[5];
    const float* b_dec_att = (const float*)d_in[6];
    const float* w_full    = (const float*)d_in[7];
    const float* b_full    = (const float*)d_in[8];
    const float* emb       = (const float*)d_in[9];
    const float* W_ih      = (const float*)d_in[10];
    const float* W_hh      = (const float*)d_in[11];
    const float* b_ih      = (const float*)d_in[12];
    const float* b_hh      = (const float*)d_in[13];
    const float* W_init_h  = (const float*)d_in[14];
    const float* b_init_h  = (const float*)d_in[15];
    const float* W_init_c  = (const float*)d_in[16];
    const float* b_init_c  = (const float*)d_in[17];
    const float* W_beta    = (const float*)d_in[18];
    const float* b_beta    = (const float*)d_in[19];
    const float* W_fc      = (const float*)d_in[20];
    const float* b_fc      = (const float*)d_in[21];
    float* out = (float*)d_out;

    float *enc, *att1, *mean, *h, *c, *Hall, *xprj, *bsum, *Wihx;
    int *capx, *rowA, *rowO, *nact;
    unsigned *cnt, *rel;
    cudaGetSymbolAddress((void**)&enc,  g_enc);
    cudaGetSymbolAddress((void**)&att1, g_att1);
    cudaGetSymbolAddress((void**)&mean, g_mean);
    cudaGetSymbolAddress((void**)&h,    g_h);
    cudaGetSymbolAddress((void**)&c,    g_c);
    cudaGetSymbolAddress((void**)&Hall, g_Hall);
    cudaGetSymbolAddress((void**)&xprj, g_xprj);
    cudaGetSymbolAddress((void**)&bsum, g_bsum);
    cudaGetSymbolAddress((void**)&Wihx, g_Wihx);
    cudaGetSymbolAddress((void**)&capx, g_capx);
    cudaGetSymbolAddress((void**)&rowA, g_rowA);
    cudaGetSymbolAddress((void**)&rowO, g_rowO);
    cudaGetSymbolAddress((void**)&nact, g_nact);
    cudaGetSymbolAddress((void**)&cnt,  g_cnt);
    cudaGetSymbolAddress((void**)&rel,  g_rel);

    cudaMemsetAsync(out, 0, (size_t)out_size * sizeof(float));
    cudaMemsetAsync(cnt, 0, sizeof(unsigned));
    cudaMemsetAsync(rel, 0, sizeof(unsigned));

    transpose_enc<<<dim3(16, 8, 64), dim3(32, 8)>>>(eo, enc);
    mean_kernel<<<4096, dim3(32, 8)>>>(eo, mean);
    setup_kernel<<<1, 256>>>(caps, lens, b_ih, b_hh);

    // att1 = enc @ W_enc_att^T + b  (M=16384, N=512, K=512)  [tensor cores]
    tgemm<<<dim3(128, 8), 256>>>(enc, 512, nullptr, W_enc_att, 512, b_enc_att,
                                 att1, 512, nullptr, NB * NP, nullptr, 512);

    wcat_kernel<<<3072, 256>>>(W_dec_att, W_beta, W_hh, W_ih);

    sgemm64<<<dim3(1, 8), 256>>>(mean, 512, W_init_h, 512, b_init_h, h, 512, 512);
    sgemm64<<<dim3(1, 8), 256>>>(mean, 512, W_init_c, 512, b_init_c, c, 512, 512);

    // x_proj = emb[cap] @ Wihx^T + bsum  (M=1984, N=2048, K=256)  [tensor cores]
    tgemm<<<dim3(16, 32), 256>>>(emb, 256, capx, Wihx, 256, bsum,
                                 xprj, 2048, nullptr, NT * NB, nullptr, 256);

    // fused 31-step recurrence (persistent, best-measured variant)
    recurrence_kernel<<<GRIDN, 256>>>(eo, b_dec_att, w_full, b_full, b_beta);

    // Final FC over compacted active rows  (M=n_act, N=16000, K=512) [tensor cores]
    tgemm<<<dim3(16, 250), 256>>>(Hall, 512, rowA, W_fc, 512, b_fc,
                                  out, NV, rowO, NT * NB, nact, 512);
}

// round 14
// speedup vs baseline: 1.5925x; 1.1333x over previous
#include <cuda_runtime.h>
#include <cuda_bf16.h>
#include <stdint.h>
#include <math.h>

// Problem constants
#define NB   64     // batch
#define NL   32     // caption length
#define NT   31     // decode steps = L-1
#define NV   16000  // vocab
#define NE   512    // ENC = DEC = ATT
#define NP   256    // pixels

#define GRIDN 128   // persistent kernel blocks (co-resident, 1 per SM)

// ---------------- device scratch (no allocation allowed) ----------------
__device__ float g_enc [NB * NP * NE];        // [B][P][C]
__device__ float g_att1[NB * NP * NE];        // [B][P][A]
__device__ float g_mean[NB * NE];
__device__ float g_h   [NB * NE];
__device__ float g_c   [NB * NE];
__device__ float g_Hall[NT * NB * NE];        // h2 per step
__device__ float g_xprj[NT * NB * 2048];      // emb gates (INTERLEAVED 4d+g) + biases
__device__ float g_pA  [4 * NB * 3072];       // phase-A k-split partials
__device__ float g_pC  [4 * NB * 2048];       // phase-C k-split partials
__device__ float g_e   [NB * NP];             // attention scores
__device__ float g_awe [NB * NE];
__device__ float g_WA  [3072 * 512];          // [Wdec; Wbeta; Whh interleaved 4d+g]
__device__ float g_WCD [2048 * 512];          // Wih[:,256:768] rows interleaved 4d+g
__device__ float g_Wihx[2048 * 256];          // Wih[:,0:256]   rows interleaved 4d+g
__device__ float g_bsum[2048];                // (b_ih+b_hh) interleaved 4d+g
__device__ int   g_capx[2048];                // emb row per (t,b)
__device__ int   g_rowA[2048];                // active row -> t*64+b (into Hall)
__device__ int   g_rowO[2048];                // active row -> b*31+t (into out)
__device__ int   g_nact[1];
__device__ unsigned g_cnt;                    // barrier arrivals
__device__ unsigned g_rel;                    // barrier release phase

__device__ __forceinline__ float sigf(float x) { return 1.0f / (1.0f + expf(-x)); }

// ============================================================================
// Tensor-core GEMM, bf16 hi/lo split (~4e-6 rel err), LDSM + packed STS path.
// C[M,N] = A[M,K] * B[N,K]^T (+bias), A rows gathered, C rows scattered.
// Tile 128x64, BK=16, 256 threads = 8 warps (4m x 2n).
// ============================================================================
#define MMA_BF16(d, A0, A1, A2, A3, B0, B1)                                   \
    asm volatile("mma.sync.aligned.m16n8k16.row.col.f32.bf16.bf16.f32 "       \
                 "{%0,%1,%2,%3}, {%4,%5,%6,%7}, {%8,%9}, {%0,%1,%2,%3};"      \
                 : "+f"(d[0]), "+f"(d[1]), "+f"(d[2]), "+f"(d[3])             \
                 : "r"(A0), "r"(A1), "r"(A2), "r"(A3), "r"(B0), "r"(B1))

#define LDSM_X4(r0, r1, r2, r3, addr)                                         \
    asm volatile("ldmatrix.sync.aligned.m8n8.x4.shared.b16 {%0,%1,%2,%3}, [%4];" \
                 : "=r"(r0), "=r"(r1), "=r"(r2), "=r"(r3) : "r"(addr))

// split float4 into packed hi/lo bf16 pairs; one 8B store each
__device__ __forceinline__ void bsplit4p(void* hip, void* lop, float4 v)
{
    float f[4] = {v.x, v.y, v.z, v.w};
    unsigned hh[2], ll[2];
#pragma unroll
    for (int i = 0; i < 2; i++) {
        __nv_bfloat16 h0 = __float2bfloat16(f[2 * i]);
        __nv_bfloat16 h1 = __float2bfloat16(f[2 * i + 1]);
        __nv_bfloat16 l0 = __float2bfloat16(f[2 * i]     - __bfloat162float(h0));
        __nv_bfloat16 l1 = __float2bfloat16(f[2 * i + 1] - __bfloat162float(h1));
        hh[i] = (unsigned)__bfloat16_as_ushort(h0) | ((unsigned)__bfloat16_as_ushort(h1) << 16);
        ll[i] = (unsigned)__bfloat16_as_ushort(l0) | ((unsigned)__bfloat16_as_ushort(l1) << 16);
    }
    *(uint2*)hip = make_uint2(hh[0], hh[1]);
    *(uint2*)lop = make_uint2(ll[0], ll[1]);
}

#define TROW 24   // padded row length in bf16 (48B stride: conflict-free LDSM)

__global__ void __launch_bounds__(256, 2)
tgemm(const float* __restrict__ A, int lda, const int* __restrict__ arow,
      const float* __restrict__ B, int ldb, const float* __restrict__ bias,
      float* __restrict__ C, int ldc, const int* __restrict__ crow,
      int M, const int* __restrict__ Mdev, int K)
{
    int Mv = Mdev ? *Mdev : M;
    int m0 = blockIdx.x * 128;
    if (m0 >= Mv) return;
    int n0 = blockIdx.y * 64;

    __shared__ __nv_bfloat16 Ah[128][TROW], Al[128][TROW];
    __shared__ __nv_bfloat16 Bh[64][TROW],  Bl[64][TROW];

    int tid = threadIdx.x;
    int warp = tid >> 5, lane = tid & 31;
    int g = lane >> 2, t4 = lane & 3;
    int wm = warp >> 1, wn = warp & 1;

    // global loaders: A rows (tid>>2), (tid>>2)+64; B row tid>>2; k-quad (tid&3)*4
    int lr = tid >> 2;
    int ak = (tid & 3) * 4;
    int r0 = m0 + lr, r1 = m0 + lr + 64;
    int c0r = (r0 < Mv) ? r0 : Mv - 1;
    int c1r = (r1 < Mv) ? r1 : Mv - 1;
    int ga0 = arow ? arow[c0r] : c0r;
    int ga1 = arow ? arow[c1r] : c1r;
    const float* Ap0 = A + (long long)ga0 * lda + ak;
    const float* Ap1 = A + (long long)ga1 * lda + ak;
    const float* Bp  = B + (long long)(n0 + lr) * ldb + ak;

    // LDSM addresses (constant across k-tiles)
    int arw = lane & 15;               // row within strip
    int ac8 = (lane >> 4) * 8;         // col half
    unsigned aAH[2], aAL[2];
#pragma unroll
    for (int s = 0; s < 2; s++) {
        int rr = wm * 32 + s * 16 + arw;
        aAH[s] = (unsigned)__cvta_generic_to_shared(&Ah[rr][ac8]);
        aAL[s] = (unsigned)__cvta_generic_to_shared(&Al[rr][ac8]);
    }
    int brw = ((lane >> 4) ? 8 : 0) + (lane & 7);
    int bc8 = ((lane >> 3) & 1) * 8;
    unsigned aBH[2], aBL[2];
#pragma unroll
    for (int p = 0; p < 2; p++) {
        int rr = wn * 32 + p * 16 + brw;
        aBH[p] = (unsigned)__cvta_generic_to_shared(&Bh[rr][bc8]);
        aBL[p] = (unsigned)__cvta_generic_to_shared(&Bl[rr][bc8]);
    }

    float acc[2][4][4];
#pragma unroll
    for (int s = 0; s < 2; s++)
#pragma unroll
        for (int nt = 0; nt < 4; nt++)
#pragma unroll
            for (int i = 0; i < 4; i++) acc[s][nt][i] = 0.0f;

    float4 av0 = *(const float4*)Ap0;
    float4 av1 = *(const float4*)Ap1;
    float4 bv  = *(const float4*)Bp;

    int ntiles = K >> 4;
    for (int t = 0; t < ntiles; t++) {
        __syncthreads();                       // prev tile's frags consumed
        bsplit4p(&Ah[lr][ak],      &Al[lr][ak],      av0);
        bsplit4p(&Ah[lr + 64][ak], &Al[lr + 64][ak], av1);
        bsplit4p(&Bh[lr][ak],      &Bl[lr][ak],      bv);
        __syncthreads();

        if (t + 1 < ntiles) {                  // prefetch next k-tile
            int kk = (t + 1) << 4;
            av0 = *(const float4*)(Ap0 + kk);
            av1 = *(const float4*)(Ap1 + kk);
            bv  = *(const float4*)(Bp + kk);
        }

        // B fragments: 2 LDSM.x4 each for hi/lo (covers 4 n-tiles)
        uint32_t bh[4][2], bl[4][2];
#pragma unroll
        for (int p = 0; p < 2; p++) {
            LDSM_X4(bh[2 * p][0], bh[2 * p][1], bh[2 * p + 1][0], bh[2 * p + 1][1], aBH[p]);
            LDSM_X4(bl[2 * p][0], bl[2 * p][1], bl[2 * p + 1][0], bl[2 * p + 1][1], aBL[p]);
        }
#pragma unroll
        for (int s = 0; s < 2; s++) {
            uint32_t ah0, ah1, ah2, ah3, al0, al1, al2, al3;
            LDSM_X4(ah0, ah1, ah2, ah3, aAH[s]);
            LDSM_X4(al0, al1, al2, al3, aAL[s]);
#pragma unroll
            for (int nt = 0; nt < 4; nt++) {
                MMA_BF16(acc[s][nt], ah0, ah1, ah2, ah3, bh[nt][0], bh[nt][1]);
                MMA_BF16(acc[s][nt], ah0, ah1, ah2, ah3, bl[nt][0], bl[nt][1]);
                MMA_BF16(acc[s][nt], al0, al1, al2, al3, bh[nt][0], bh[nt][1]);
            }
        }
    }

    // epilogue
#pragma unroll
    for (int s = 0; s < 2; s++) {
#pragma unroll
        for (int half = 0; half < 2; half++) {      // c0/c1 then c2/c3 (row +8)
            int r = m0 + wm * 32 + s * 16 + g + half * 8;
            if (r >= Mv) continue;
            int cr = crow ? crow[r] : r;
#pragma unroll
            for (int nt = 0; nt < 4; nt++) {
                int col = n0 + wn * 32 + nt * 8 + 2 * t4;
                float2 v;
                v.x = acc[s][nt][half * 2 + 0];
                v.y = acc[s][nt][half * 2 + 1];
                if (bias) { v.x += bias[col]; v.y += bias[col + 1]; }
                *(float2*)(C + (long long)cr * ldc + col) = v;
            }
        }
    }
}

// ---------------- small tiled SGEMM (h0/c0 only) ----------------------------
__global__ void sgemm64(const float* __restrict__ A, int lda,
                        const float* __restrict__ B, int ldb,
                        const float* __restrict__ bias,
                        float* __restrict__ C, int ldc, int K)
{
    int n0 = blockIdx.y * 64;
    __shared__ float As[16][68];
    __shared__ float Bs[16][68];

    int tid = threadIdx.x;
    int tx = tid & 15, ty = tid >> 4;
    int lm = tid >> 2, lk = (tid & 3) * 4;

    const float* Arow = A + (long long)lm * lda;
    const float* Brow = B + (long long)(n0 + lm) * ldb;

    float acc[4][4];
#pragma unroll
    for (int i = 0; i < 4; i++)
#pragma unroll
        for (int j = 0; j < 4; j++) acc[i][j] = 0.0f;

    for (int kk = 0; kk < K; kk += 16) {
        float4 av = *(const float4*)(Arow + kk + lk);
        float4 bv = *(const float4*)(Brow + kk + lk);
        __syncthreads();
        As[lk + 0][lm] = av.x; As[lk + 1][lm] = av.y;
        As[lk + 2][lm] = av.z; As[lk + 3][lm] = av.w;
        Bs[lk + 0][lm] = bv.x; Bs[lk + 1][lm] = bv.y;
        Bs[lk + 2][lm] = bv.z; Bs[lk + 3][lm] = bv.w;
        __syncthreads();
#pragma unroll
        for (int k = 0; k < 16; k++) {
            float4 a4 = *(const float4*)&As[k][ty * 4];
            float4 b4 = *(const float4*)&Bs[k][tx * 4];
            float aa[4] = {a4.x, a4.y, a4.z, a4.w};
            float bb[4] = {b4.x, b4.y, b4.z, b4.w};
#pragma unroll
            for (int i = 0; i < 4; i++)
#pragma unroll
                for (int j = 0; j < 4; j++) acc[i][j] = fmaf(aa[i], bb[j], acc[i][j]);
        }
    }

#pragma unroll
    for (int i = 0; i < 4; i++) {
        float* Cp = C + (long long)(ty * 4 + i) * ldc + n0 + tx * 4;
#pragma unroll
        for (int j = 0; j < 4; j++)
            Cp[j] = acc[i][j] + bias[n0 + tx * 4 + j];
    }
}

// ---------------- transpose encoder_out [B][C][P] -> enc [B][P][C] ----------
__global__ void transpose_enc(const float* __restrict__ eo, float* __restrict__ enc)
{
    __shared__ float t[32][33];
    int b = blockIdx.z;
    int c0 = blockIdx.x * 32, p0 = blockIdx.y * 32;
    int x = threadIdx.x, y = threadIdx.y;
    for (int i = y; i < 32; i += 8)
        t[i][x] = eo[((long long)b * NE + c0 + i) * NP + p0 + x];
    __syncthreads();
    for (int i = y; i < 32; i += 8)
        enc[((long long)b * NP + p0 + i) * NE + c0 + x] = t[x][i];
}

// ---------------- mean over pixels ------------------------------------------
__global__ void mean_kernel(const float* __restrict__ eo, float* __restrict__ mean)
{
    int row = blockIdx.x * 8 + threadIdx.y;
    int lane = threadIdx.x;
    const float* src = eo + (long long)row * NP;
    float s = 0.0f;
    for (int p = lane; p < NP; p += 32) s += src[p];
#pragma unroll
    for (int o = 16; o > 0; o >>= 1) s += __shfl_xor_sync(0xffffffffu, s, o);
    if (lane == 0) mean[row] = s * (1.0f / NP);
}

// ---------------- setup ------------------------------------------------------
__global__ void setup_kernel(const int* __restrict__ caps, const int* __restrict__ lens,
                             const float* __restrict__ b_ih, const float* __restrict__ b_hh)
{
    int tid = threadIdx.x;
    for (int j = tid; j < 2048; j += 256) {
        int d = j >> 2, g = j & 3;                 // interleaved 4d+g
        g_bsum[j] = b_ih[g * 512 + d] + b_hh[g * 512 + d];
    }
    for (int i = tid; i < NT * NB; i += 256) {
        int t = i / NB, b = i % NB;
        g_capx[i] = caps[b * NL + t];
    }
    __syncthreads();
    if (tid == 0) {
        int cnt = 0;
        for (int t = 0; t < NT; t++)
            for (int b = 0; b < NB; b++)
                if (t < lens[b] - 1) { g_rowA[cnt] = t * NB + b; g_rowO[cnt] = b * NT + t; cnt++; }
        g_nact[0] = cnt;
        for (int i = cnt; i < 2048; i++) { g_rowA[i] = 0; g_rowO[i] = 0; }
    }
}

// ---------------- build stacked/interleaved weights -------------------------
__global__ void wcat_kernel(const float* __restrict__ Wd, const float* __restrict__ Wb,
                            const float* __restrict__ Whh, const float* __restrict__ Wih)
{
    int f4 = blockIdx.x * blockDim.x + threadIdx.x;
    if (f4 < 3072 * 128) {
        int n = f4 >> 7, q = (f4 & 127) * 4;
        const float* src;
        if (n < 512)       src = Wd + n * 512 + q;
        else if (n < 1024) src = Wb + (n - 512) * 512 + q;
        else {
            int m = n - 1024, d = m >> 2, g = m & 3;
            src = Whh + (g * 512 + d) * 512 + q;
        }
        *(float4*)(g_WA + f4 * 4) = *(const float4*)src;
    } else if (f4 < 3072 * 128 + 2048 * 128) {
        int r = f4 - 3072 * 128;
        int n = r >> 7, q = (r & 127) * 4;
        int d = n >> 2, g = n & 3;
        *(float4*)(g_WCD + r * 4) = *(const float4*)(Wih + (g * 512 + d) * 768 + 256 + q);
    } else {
        int r = f4 - 3072 * 128 - 2048 * 128;
        if (r >= 2048 * 64) return;
        int n = r >> 6, q = (r & 63) * 4;
        int d = n >> 2, g = n & 3;
        *(float4*)(g_Wihx + r * 4) = *(const float4*)(Wih + (g * 512 + d) * 768 + q);
    }
}

// ============================================================================
// PERSISTENT RECURRENCE KERNEL — exact best-measured (2460us) version
// ============================================================================
__device__ __forceinline__ void gbar(unsigned target)
{
    __syncthreads();
    if (threadIdx.x == 0) {
        __threadfence();
        unsigned p = atomicAdd(&g_cnt, 1u);
        if (p == target * GRIDN - 1u) {
            atomicExch(&g_rel, target);
        } else {
            volatile unsigned* rel = &g_rel;
            while (*rel < target) { }
        }
        __threadfence();
    }
    __syncthreads();
}

__global__ void __launch_bounds__(256, 1)
recurrence_kernel(const float* __restrict__ eo,
                  const float* __restrict__ b_dec_att,
                  const float* __restrict__ w_full,
                  const float* __restrict__ b_full,
                  const float* __restrict__ b_beta)
{
    __shared__ float sh[2560];
    int blk = blockIdx.x;
    int tid = threadIdx.x;

    for (int t = 0; t < NT; t++) {
        unsigned base = (unsigned)(t * 5);

        // ======== Phase A: pA[kz] = h @ WA^T partial (96-col tile, 4b x 6n) =====
        {
            int nt = blk & 31;
            int kz = blk >> 5;
            int k0 = kz * 128;
            float (*As)[64] = (float(*)[64])sh;
            float (*Ws)[96] = (float(*)[96])(sh + 1024);
            int bi = tid & 15;
            int ci = tid >> 4;
            int lrow = tid >> 2, lk = (tid & 3) * 4;
            int wn2 = (tid >> 2) + 64, wk = (tid & 3) * 4;

            float acc[4][6];
#pragma unroll
            for (int i = 0; i < 4; i++)
#pragma unroll
                for (int j = 0; j < 6; j++) acc[i][j] = 0.0f;

            const float* Wbase = g_WA + (long long)nt * 96 * 512 + k0;
            for (int kk = 0; kk < 128; kk += 16) {
                float4 hv = *(const float4*)(g_h + lrow * 512 + k0 + kk + lk);
                float4 w1 = *(const float4*)(Wbase + (long long)lrow * 512 + kk + lk);
                float4 w2 = make_float4(0, 0, 0, 0);
                if (tid < 128)
                    w2 = *(const float4*)(Wbase + (long long)wn2 * 512 + kk + wk);
                __syncthreads();
                As[lk + 0][lrow] = hv.x; As[lk + 1][lrow] = hv.y;
                As[lk + 2][lrow] = hv.z; As[lk + 3][lrow] = hv.w;
                Ws[lk + 0][lrow] = w1.x; Ws[lk + 1][lrow] = w1.y;
                Ws[lk + 2][lrow] = w1.z; Ws[lk + 3][lrow] = w1.w;
                if (tid < 128) {
                    Ws[wk + 0][wn2] = w2.x; Ws[wk + 1][wn2] = w2.y;
                    Ws[wk + 2][wn2] = w2.z; Ws[wk + 3][wn2] = w2.w;
                }
                __syncthreads();
#pragma unroll
                for (int k = 0; k < 16; k++) {
                    float a[4], w[6];
                    *(float4*)a = *(const float4*)&As[k][bi * 4];
                    *(float2*)(w)     = *(const float2*)&Ws[k][ci * 6];
                    *(float2*)(w + 2) = *(const float2*)&Ws[k][ci * 6 + 2];
                    *(float2*)(w + 4) = *(const float2*)&Ws[k][ci * 6 + 4];
#pragma unroll
                    for (int i = 0; i < 4; i++)
#pragma unroll
                        for (int j = 0; j < 6; j++)
                            acc[i][j] = fmaf(a[i], w[j], acc[i][j]);
                }
                __syncthreads();
            }
            float* dst = g_pA + ((long long)kz * NB) * 3072 + nt * 96 + ci * 6;
#pragma unroll
            for (int i = 0; i < 4; i++) {
                float* row = dst + (long long)(bi * 4 + i) * 3072;
#pragma unroll
                for (int j = 0; j < 6; j += 2)
                    *(float2*)(row + j) = make_float2(acc[i][j], acc[i][j + 1]);
            }
        }
        gbar(base + 1);

        // ======== Phase B1: e[b][p] scores (b x p-half per block) ================
        {
            int b = blk >> 1, half = blk & 1;
            float* att2_s = sh;
            float* w_s    = sh + 512;
            for (int a = tid; a < 512; a += 256) {
                float v = b_dec_att[a];
#pragma unroll
                for (int kz = 0; kz < 4; kz++)
                    v += g_pA[((long long)kz * NB + b) * 3072 + a];
                att2_s[a] = v;
                w_s[a] = w_full[a];
            }
            __syncthreads();

            int pl = tid >> 1;
            int p  = half * 128 + pl;
            int ao = (tid & 1) * 256;
            const float* arow = g_att1 + ((long long)b * NP + p) * NE + ao;
            float acc = 0.0f;
#pragma unroll 4
            for (int a = 0; a < 256; a += 4) {
                float4 v4 = *(const float4*)(arow + a);
                acc = fmaf(fmaxf(v4.x + att2_s[ao + a + 0], 0.0f), w_s[ao + a + 0], acc);
                acc = fmaf(fmaxf(v4.y + att2_s[ao + a + 1], 0.0f), w_s[ao + a + 1], acc);
                acc = fmaf(fmaxf(v4.z + att2_s[ao + a + 2], 0.0f), w_s[ao + a + 2], acc);
                acc = fmaf(fmaxf(v4.w + att2_s[ao + a + 3], 0.0f), w_s[ao + a + 3], acc);
            }
            acc += __shfl_xor_sync(0xffffffffu, acc, 1);
            if ((tid & 1) == 0) g_e[b * NP + p] = acc + b_full[0];
        }
        gbar(base + 2);

        // ======== Phase B2: softmax + gated awe (b x c-half per block) ===========
        {
            int b = blk >> 1, ch = blk & 1;
            float* es     = sh;
            float* red_s  = sh + 256;
            float* alpha_s= sh + 512;
            es[tid] = g_e[b * NP + tid];
            __syncthreads();
            red_s[tid] = es[tid]; __syncthreads();
            for (int s = 128; s > 0; s >>= 1) {
                if (tid < s) red_s[tid] = fmaxf(red_s[tid], red_s[tid + s]);
                __syncthreads();
            }
            float mx = red_s[0]; __syncthreads();
            float ex = expf(es[tid] - mx);
            red_s[tid] = ex; __syncthreads();
            for (int s = 128; s > 0; s >>= 1) {
                if (tid < s) red_s[tid] += red_s[tid + s];
                __syncthreads();
            }
            alpha_s[tid] = ex / red_s[0];
            __syncthreads();

            int c = ch * 256 + tid;
            const float* erow = eo + ((long long)b * NE + c) * NP;
            float s = 0.0f;
#pragma unroll 4
            for (int p = 0; p < NP; p += 4) {
                float4 e4 = *(const float4*)(erow + p);
                s = fmaf(e4.x, alpha_s[p + 0], s);
                s = fmaf(e4.y, alpha_s[p + 1], s);
                s = fmaf(e4.z, alpha_s[p + 2], s);
                s = fmaf(e4.w, alpha_s[p + 3], s);
            }
            float gpre = b_beta[c];
#pragma unroll
            for (int kz = 0; kz < 4; kz++)
                gpre += g_pA[((long long)kz * NB + b) * 3072 + 512 + c];
            g_awe[b * NE + c] = sigf(gpre) * s;
        }
        gbar(base + 3);

        // ======== Phase C: pC[kz] = awe @ WCD^T partial (64-col tile, 4b x 4n) ===
        {
            int nt = blk & 31;
            int kz = blk >> 5;
            int k0 = kz * 128;
            float (*As)[64] = (float(*)[64])sh;
            float (*Ws)[64] = (float(*)[64])(sh + 1024);
            int bi = tid & 15;
            int ci = tid >> 4;
            int lrow = tid >> 2, lk = (tid & 3) * 4;

            float acc[4][4];
#pragma unroll
            for (int i = 0; i < 4; i++)
#pragma unroll
                for (int j = 0; j < 4; j++) acc[i][j] = 0.0f;

            const float* Wbase = g_WCD + (long long)nt * 64 * 512 + k0;
            for (int kk = 0; kk < 128; kk += 16) {
                float4 av = *(const float4*)(g_awe + lrow * 512 + k0 + kk + lk);
                float4 wv = *(const float4*)(Wbase + (long long)lrow * 512 + kk + lk);
                __syncthreads();
                As[lk + 0][lrow] = av.x; As[lk + 1][lrow] = av.y;
                As[lk + 2][lrow] = av.z; As[lk + 3][lrow] = av.w;
                Ws[lk + 0][lrow] = wv.x; Ws[lk + 1][lrow] = wv.y;
                Ws[lk + 2][lrow] = wv.z; Ws[lk + 3][lrow] = wv.w;
                __syncthreads();
#pragma unroll
                for (int k = 0; k < 16; k++) {
                    float a[4], w[4];
                    *(float4*)a = *(const float4*)&As[k][bi * 4];
                    *(float4*)w = *(const float4*)&Ws[k][ci * 4];
#pragma unroll
                    for (int i = 0; i < 4; i++)
#pragma unroll
                        for (int j = 0; j < 4; j++)
                            acc[i][j] = fmaf(a[i], w[j], acc[i][j]);
                }
                __syncthreads();
            }
            float* dst = g_pC + ((long long)kz * NB) * 2048 + nt * 64 + ci * 4;
#pragma unroll
            for (int i = 0; i < 4; i++)
                *(float4*)(dst + (long long)(bi * 4 + i) * 2048) =
                    make_float4(acc[i][0], acc[i][1], acc[i][2], acc[i][3]);
        }
        gbar(base + 4);

        // ======== Phase D: reduce partials + LSTM pointwise =====================
        {
            int idx = blk * 256 + tid;
            int b = idx >> 9, d = idx & 511;
            float4 gv = *(const float4*)(g_xprj + (((long long)t * NB + b) * 2048) + 4 * d);
            float gi = gv.x, gf = gv.y, gg = gv.z, go = gv.w;
#pragma unroll
            for (int kz = 0; kz < 4; kz++) {
                float4 pa = *(const float4*)(g_pA + ((long long)kz * NB + b) * 3072 + 1024 + 4 * d);
                float4 pc = *(const float4*)(g_pC + ((long long)kz * NB + b) * 2048 + 4 * d);
                gi += pa.x + pc.x; gf += pa.y + pc.y;
                gg += pa.z + pc.z; go += pa.w + pc.w;
            }
            float cp = g_c[b * NE + d];
            float cn = sigf(gf) * cp + sigf(gi) * tanhf(gg);
            float hn = sigf(go) * tanhf(cn);
            g_c[b * NE + d] = cn;
            g_h[b * NE + d] = hn;
            g_Hall[((long long)t * NB + b) * NE + d] = hn;
        }
        gbar(base + 5);
    }
}

// ---------------- host launch -----------------------------------------------
extern "C" void kernel_launch(void* const* d_in, const int* in_sizes, int n_in,
                              void* d_out, int out_size)
{
    const float* eo        = (const float*)d_in[0];
    const int*   caps      = (const int*)  d_in[1];
    const int*   lens      = (const int*)  d_in[2];
    const float* W_enc_att = (const float*)d_in[3];
    const float* b_enc_att = (const float*)d_in[4];
    const float* W_dec_att = (const float*)d_in[5];
    const float* b_dec_att = (const float*)d_in[6];
    const float* w_full    = (const float*)d_in[7];
    const float* b_full    = (const float*)d_in[8];
    const float* emb       = (const float*)d_in[9];
    const float* W_ih      = (const float*)d_in[10];
    const float* W_hh      = (const float*)d_in[11];
    const float* b_ih      = (const float*)d_in[12];
    const float* b_hh      = (const float*)d_in[13];
    const float* W_init_h  = (const float*)d_in[14];
    const float* b_init_h  = (const float*)d_in[15];
    const float* W_init_c  = (const float*)d_in[16];
    const float* b_init_c  = (const float*)d_in[17];
    const float* W_beta    = (const float*)d_in[18];
    const float* b_beta    = (const float*)d_in[19];
    const float* W_fc      = (const float*)d_in[20];
    const float* b_fc      = (const float*)d_in[21];
    float* out = (float*)d_out;

    float *enc, *att1, *mean, *h, *c, *Hall, *xprj, *bsum, *Wihx;
    int *capx, *rowA, *rowO, *nact;
    unsigned *cnt, *rel;
    cudaGetSymbolAddress((void**)&enc,  g_enc);
    cudaGetSymbolAddress((void**)&att1, g_att1);
    cudaGetSymbolAddress((void**)&mean, g_mean);
    cudaGetSymbolAddress((void**)&h,    g_h);
    cudaGetSymbolAddress((void**)&c,    g_c);
    cudaGetSymbolAddress((void**)&Hall, g_Hall);
    cudaGetSymbolAddress((void**)&xprj, g_xprj);
    cudaGetSymbolAddress((void**)&bsum, g_bsum);
    cudaGetSymbolAddress((void**)&Wihx, g_Wihx);
    cudaGetSymbolAddress((void**)&capx, g_capx);
    cudaGetSymbolAddress((void**)&rowA, g_rowA);
    cudaGetSymbolAddress((void**)&rowO, g_rowO);
    cudaGetSymbolAddress((void**)&nact, g_nact);
    cudaGetSymbolAddress((void**)&cnt,  g_cnt);
    cudaGetSymbolAddress((void**)&rel,  g_rel);

    cudaMemsetAsync(out, 0, (size_t)out_size * sizeof(float));
    cudaMemsetAsync(cnt, 0, sizeof(unsigned));
    cudaMemsetAsync(rel, 0, sizeof(unsigned));

    transpose_enc<<<dim3(16, 8, 64), dim3(32, 8)>>>(eo, enc);
    mean_kernel<<<4096, dim3(32, 8)>>>(eo, mean);
    setup_kernel<<<1, 256>>>(caps, lens, b_ih, b_hh);

    // att1 = enc @ W_enc_att^T + b  (M=16384, N=512, K=512)  [tensor cores]
    tgemm<<<dim3(128, 8), 256>>>(enc, 512, nullptr, W_enc_att, 512, b_enc_att,
                                 att1, 512, nullptr, NB * NP, nullptr, 512);

    wcat_kernel<<<3072, 256>>>(W_dec_att, W_beta, W_hh, W_ih);

    sgemm64<<<dim3(1, 8), 256>>>(mean, 512, W_init_h, 512, b_init_h, h, 512, 512);
    sgemm64<<<dim3(1, 8), 256>>>(mean, 512, W_init_c, 512, b_init_c, c, 512, 512);

    // x_proj = emb[cap] @ Wihx^T + bsum  (M=1984, N=2048, K=256)  [tensor cores]
    tgemm<<<dim3(16, 32), 256>>>(emb, 256, capx, Wihx, 256, bsum,
                                 xprj, 2048, nullptr, NT * NB, nullptr, 256);

    // fused 31-step recurrence (persistent, best-measured variant)
    recurrence_kernel<<<GRIDN, 256>>>(eo, b_dec_att, w_full, b_full, b_beta);

    // Final FC over compacted active rows  (M=n_act, N=16000, K=512) [tensor cores]
    tgemm<<<dim3(16, 250), 256>>>(Hall, 512, rowA, W_fc, 512, b_fc,
                                  out, NV, rowO, NT * NB, nact, 512);
}